// round 14
// baseline (speedup 1.0000x reference)
#include <cuda_runtime.h>
#include <math.h>

// Problem constants (fixed by setup_inputs: B=4, N=2048, D_MODEL=512)
#define N_PTS   2048
#define N_WAVES 256              // D_MODEL / 2
#define T       16               // tile rows
#define HJ      8                // jj-half width (j accums live per half)
#define NT      (N_PTS / T)      // 128 tiles
#define W       16               // j-tiles per strip
#define NSTRIPS (NT / W)         // 8
#define F_MUFU  13               // ii < F_MUFU -> MUFU path, else FMA poly path

typedef unsigned long long ull;

__device__ __forceinline__ void red_add_v2(float* p, float x, float y) {
    asm volatile("red.global.add.v2.f32 [%0], {%1, %2};"
                 :: "l"(p), "f"(x), "f"(y) : "memory");
}
__device__ __forceinline__ ull pack2(float lo, float hi) {
    ull v; asm("mov.b64 %0, {%1, %2};" : "=l"(v) : "f"(lo), "f"(hi)); return v;
}
__device__ __forceinline__ void unpack2(ull v, float& lo, float& hi) {
    asm("mov.b64 {%0, %1}, %2;" : "=f"(lo), "=f"(hi) : "l"(v));
}
__device__ __forceinline__ ull fma2(ull a, ull b, ull c) {
    ull d; asm("fma.rn.f32x2 %0, %1, %2, %3;" : "=l"(d) : "l"(a), "l"(b), "l"(c));
    return d;
}
__device__ __forceinline__ ull mul2(ull a, ull b) {
    ull d; asm("mul.rn.f32x2 %0, %1, %2;" : "=l"(d) : "l"(a), "l"(b));
    return d;
}

__global__ __launch_bounds__(256, 4) void spatial_embedding_sym_kernel(
    const float* __restrict__ coords,          // (B, N, 3)
    const unsigned char* __restrict__ mask,    // (B, N) bool, 1 = padded
    float* __restrict__ out)                   // (B, N, 512), pre-zeroed
{
    // Pair table: (r, amp) only. amp = 1/(4*pi*r)*vi*vj, zeroed at self-pairs.
    // j-side uses the SAME amp: it is wrong only on the diagonal tile, whose
    // j-side flush is skipped entirely, so the error is never observed.
    __shared__ float2 sh2[2][T * T];           // double-buffered (r, amp)
    __shared__ float sxi[T], syi[T], szi[T], svi[T];

    const int strip = blockIdx.x;
    const int ti    = blockIdx.y;
    const int b     = blockIdx.z;
    const int tid   = threadIdx.x;             // wave index m

    const int tj_end = strip * W + W;
    if (tj_end <= ti) return;                  // strip entirely below diagonal
    const int tj_beg = (ti > strip * W) ? ti : strip * W;

    const float* cb = coords + (size_t)b * N_PTS * 3;
    const unsigned char* mb = mask + (size_t)b * N_PTS;

    // k_m = 2*pi / lam_m, lam = geomspace(2, 100, 256); double to match numpy
    const double tt = (double)tid / (double)(N_WAVES - 1);
    const float  k  = (float)(6.283185307179586 / (2.0 * pow(50.0, tt)));

    // packed Taylor coefficients: (cos_n, sin_n) for powers of x^2, |x|<=pi/2
    const ull P0 = pack2( 1.0f,            1.0f);
    const ull P1 = pack2(-0.5f,           -1.66666672e-1f);
    const ull P2 = pack2( 4.16666679e-2f,  8.33333358e-3f);
    const ull P3 = pack2(-1.38888893e-3f, -1.98412701e-4f);
    const ull P4 = pack2( 2.48015876e-5f,  2.75573192e-6f);
    const ull P5 = pack2(-2.75573192e-7f, -2.50521084e-8f);

    if (tid < T) {
        const int ig = ti * T + tid;
        sxi[tid] = cb[ig * 3 + 0];
        syi[tid] = cb[ig * 3 + 1];
        szi[tid] = cb[ig * 3 + 2];
        svi[tid] = (mb[ig] == 0) ? 1.0f : 0.0f;
    }

    // i-side packed (re, im) accumulators, persist across the strip (32 regs)
    ull aiP[T];
    #pragma unroll
    for (int q = 0; q < T; ++q) aiP[q] = 0ull;

    const int pa_ii = tid >> 4;                // this thread's Phase-A pair
    const int pa_jj = tid & (T - 1);

    __syncthreads();                           // sxi/svi visible

    // ---- Phase A for tile t -> sh2[t&1]; validities folded into amp ----
    #define PHASE_A(t)                                                        \
    {                                                                         \
        const int jg = (t) * T + pa_jj;                                       \
        const float xj = cb[jg * 3 + 0];                                      \
        const float yj = cb[jg * 3 + 1];                                      \
        const float zj = cb[jg * 3 + 2];                                      \
        const float vj = (mb[jg] == 0) ? 1.0f : 0.0f;                         \
        const float dx = sxi[pa_ii] - xj;                                     \
        const float dy = syi[pa_ii] - yj;                                     \
        const float dz = szi[pa_ii] - zj;                                     \
        float sq = fmaf(dx, dx, fmaf(dy, dy, dz * dz));                       \
        const bool self = ((t) == ti) && (pa_ii == pa_jj);                    \
        if (self) sq = 1.0f;                       /* sq_safe */              \
        const float rs = rsqrtf(sq);                                          \
        const float r  = sq * rs;                                             \
        const float vv = self ? 0.0f : (svi[pa_ii] * vj);                     \
        const float amp = 0.07957747154594767f * rs * vv;                     \
        sh2[(t) & 1][tid] = make_float2(r, amp);                              \
    }

    PHASE_A(tj_beg);                           // prologue
    __syncthreads();

    for (int tj = tj_beg; tj < tj_end; ++tj) {
        // pipeline: build next tile's table while sweeping current one
        if (tj + 1 < tj_end) PHASE_A(tj + 1);

        const float2* cur = sh2[tj & 1];

        // ---- Phase B: two jj-half passes, pipes interleaved per item ----
        #pragma unroll 1
        for (int h = 0; h < 2; ++h) {
            ull ajP[HJ];                      // packed (re, im) j-side accum
            #pragma unroll
            for (int q = 0; q < HJ; ++q) ajP[q] = 0ull;

            #pragma unroll
            for (int jj = 0; jj < HJ; ++jj) {
                #pragma unroll
                for (int ii = 0; ii < T; ++ii) {
                    const float2 ra = cur[ii * T + h * HJ + jj];  // LDS.64
                    const float ph = k * ra.x;
                    float s, c;
                    if (ii < F_MUFU) {
                        // MUFU path
                        s = __sinf(ph);
                        c = __cosf(ph);
                    } else {
                        // FMA path: reduce to [-pi/2, pi/2] (single-word pi:
                        // err <= |n|*8.7e-8 ~ 7e-6 rad, well under tolerance),
                        // packed Taylor, (-1)^n sign fixup on the ALU pipe
                        const float q  = fmaf(ph, 0.31830988618379067f, 12582912.0f);
                        const float nf = q - 12582912.0f;
                        const float x  = fmaf(nf, -3.14159274101257f, ph);
                        const ull xs = pack2(x, x);
                        const ull xx = mul2(xs, xs);                  // (x2, x2)
                        ull p = fma2(xx, P5, P4);
                        p = fma2(xx, p, P3);
                        p = fma2(xx, p, P2);
                        p = fma2(xx, p, P1);
                        p = fma2(xx, p, P0);                          // (cos, sin/x)
                        const ull sgn32 = (ull)((__float_as_uint(q) & 1u) << 31);
                        p ^= (sgn32 << 32) | sgn32;                   // *(-1)^n both
                        float plo, phi;
                        unpack2(p, plo, phi);
                        c = plo;
                        s = x * phi;
                    }
                    const ull cs = pack2(c, s);
                    const ull a2 = pack2(ra.y, ra.y);   // shared amp splat
                    aiP[ii] = fma2(cs, a2, aiP[ii]);
                    ajP[jj] = fma2(cs, a2, ajP[jj]);
                }
            }

            // flush this jj-half (diagonal tile skipped: its ajP is unused)
            if (tj != ti) {
                #pragma unroll
                for (int jj = 0; jj < HJ; ++jj) {
                    const int jglob = h * HJ + jj;
                    float re, im;
                    unpack2(ajP[jj], re, im);
                    float* p = out + ((size_t)(b * N_PTS) + tj * T + jglob) * (2 * N_WAVES)
                                   + 2 * tid;
                    red_add_v2(p, re, im);
                }
            }
        }

        __syncthreads();   // Phase B reads done before buffer is overwritten
    }

    // flush i-side partials once per block (validity already folded in)
    #pragma unroll
    for (int ii = 0; ii < T; ++ii) {
        float re, im;
        unpack2(aiP[ii], re, im);
        float* p = out + ((size_t)(b * N_PTS) + ti * T + ii) * (2 * N_WAVES)
                       + 2 * tid;
        red_add_v2(p, re, im);
    }
}

extern "C" void kernel_launch(void* const* d_in, const int* in_sizes, int n_in,
                              void* d_out, int out_size)
{
    const float* coords       = (const float*)d_in[0];
    const unsigned char* mask = (const unsigned char*)d_in[1];
    float* out                = (float*)d_out;

    const int BN = in_sizes[1];        // B * N
    const int B  = BN / N_PTS;

    // output is accumulated atomically -> must start from zero
    cudaMemsetAsync(d_out, 0, (size_t)out_size * sizeof(float), 0);

    dim3 grid(NSTRIPS, NT, B);
    spatial_embedding_sym_kernel<<<grid, 256>>>(coords, mask, out);
}

// round 15
// speedup vs baseline: 1.0170x; 1.0170x over previous
#include <cuda_runtime.h>
#include <math.h>

// Problem constants (fixed by setup_inputs: B=4, N=2048, D_MODEL=512)
#define N_PTS   2048
#define N_WAVES 256              // D_MODEL / 2
#define T       16               // tile rows
#define HJ      8                // jj-half width (j accums live per half)
#define NT      (N_PTS / T)      // 128 tiles
#define W       8                // j-tiles per strip
#define NSTRIPS (NT / W)         // 16
#define F_MUFU  13               // ii < F_MUFU -> MUFU path, else FMA poly path

typedef unsigned long long ull;

__device__ __forceinline__ void red_add_v2(float* p, float x, float y) {
    asm volatile("red.global.add.v2.f32 [%0], {%1, %2};"
                 :: "l"(p), "f"(x), "f"(y) : "memory");
}
__device__ __forceinline__ ull pack2(float lo, float hi) {
    ull v; asm("mov.b64 %0, {%1, %2};" : "=l"(v) : "f"(lo), "f"(hi)); return v;
}
__device__ __forceinline__ void unpack2(ull v, float& lo, float& hi) {
    asm("mov.b64 {%0, %1}, %2;" : "=f"(lo), "=f"(hi) : "l"(v));
}
__device__ __forceinline__ ull fma2(ull a, ull b, ull c) {
    ull d; asm("fma.rn.f32x2 %0, %1, %2, %3;" : "=l"(d) : "l"(a), "l"(b), "l"(c));
    return d;
}
__device__ __forceinline__ ull mul2(ull a, ull b) {
    ull d; asm("mul.rn.f32x2 %0, %1, %2;" : "=l"(d) : "l"(a), "l"(b));
    return d;
}

__global__ __launch_bounds__(256, 4) void spatial_embedding_sym_kernel(
    const float* __restrict__ coords,          // (B, N, 3)
    const unsigned char* __restrict__ mask,    // (B, N) bool, 1 = padded
    float* __restrict__ out)                   // (B, N, 512), pre-zeroed
{
    // Pair table: (r, amp) only. amp = 1/(4*pi*r)*vi*vj, zeroed at self-pairs.
    // j-side uses the SAME amp: it is wrong only on the diagonal tile, whose
    // j-side flush is skipped entirely, so the error is never observed.
    __shared__ float2 sh2[2][T * T];           // double-buffered (r, amp)
    __shared__ float sxi[T], syi[T], szi[T], svi[T];

    const int strip = blockIdx.x;
    const int ti    = blockIdx.y;
    const int b     = blockIdx.z;
    const int tid   = threadIdx.x;             // wave index m

    const int tj_end = strip * W + W;
    if (tj_end <= ti) return;                  // strip entirely below diagonal
    const int tj_beg = (ti > strip * W) ? ti : strip * W;

    const float* cb = coords + (size_t)b * N_PTS * 3;
    const unsigned char* mb = mask + (size_t)b * N_PTS;

    // k_m = 2*pi / lam_m, lam = geomspace(2, 100, 256)
    //     = pi * 50^(-t),  t = m/255
    // float exp2 with two-word log2(50): exponent exact to ~1e-8; residual
    // ~1.2e-7 rel from exp2f -> phase error <= 3e-5 rad at max k*r. OK.
    const float tf = (float)tid * (1.0f / 255.0f);
    const float e_hi = -5.64385605f;           // -(log2(50) hi)
    const float e_lo = -1.35934586e-8f;        // -(log2(50) lo)
    const float ex = fmaf(tf, e_lo, tf * e_hi);
    const float k  = 3.14159265358979f * exp2f(ex);

    // packed Taylor coefficients: (cos_n, sin_n) for powers of x^2, |x|<=pi/2
    const ull P0 = pack2( 1.0f,            1.0f);
    const ull P1 = pack2(-0.5f,           -1.66666672e-1f);
    const ull P2 = pack2( 4.16666679e-2f,  8.33333358e-3f);
    const ull P3 = pack2(-1.38888893e-3f, -1.98412701e-4f);
    const ull P4 = pack2( 2.48015876e-5f,  2.75573192e-6f);
    const ull P5 = pack2(-2.75573192e-7f, -2.50521084e-8f);

    if (tid < T) {
        const int ig = ti * T + tid;
        sxi[tid] = cb[ig * 3 + 0];
        syi[tid] = cb[ig * 3 + 1];
        szi[tid] = cb[ig * 3 + 2];
        svi[tid] = (mb[ig] == 0) ? 1.0f : 0.0f;
    }

    // i-side packed (re, im) accumulators, persist across the strip (32 regs)
    ull aiP[T];
    #pragma unroll
    for (int q = 0; q < T; ++q) aiP[q] = 0ull;

    const int pa_ii = tid >> 4;                // this thread's Phase-A pair
    const int pa_jj = tid & (T - 1);

    __syncthreads();                           // sxi/svi visible

    // ---- Phase A for tile t -> sh2[t&1]; validities folded into amp ----
    #define PHASE_A(t)                                                        \
    {                                                                         \
        const int jg = (t) * T + pa_jj;                                       \
        const float xj = cb[jg * 3 + 0];                                      \
        const float yj = cb[jg * 3 + 1];                                      \
        const float zj = cb[jg * 3 + 2];                                      \
        const float vj = (mb[jg] == 0) ? 1.0f : 0.0f;                         \
        const float dx = sxi[pa_ii] - xj;                                     \
        const float dy = syi[pa_ii] - yj;                                     \
        const float dz = szi[pa_ii] - zj;                                     \
        float sq = fmaf(dx, dx, fmaf(dy, dy, dz * dz));                       \
        const bool self = ((t) == ti) && (pa_ii == pa_jj);                    \
        if (self) sq = 1.0f;                       /* sq_safe */              \
        const float rs = rsqrtf(sq);                                          \
        const float r  = sq * rs;                                             \
        const float vv = self ? 0.0f : (svi[pa_ii] * vj);                     \
        const float amp = 0.07957747154594767f * rs * vv;                     \
        sh2[(t) & 1][tid] = make_float2(r, amp);                              \
    }

    PHASE_A(tj_beg);                           // prologue
    __syncthreads();

    for (int tj = tj_beg; tj < tj_end; ++tj) {
        // pipeline: build next tile's table while sweeping current one
        if (tj + 1 < tj_end) PHASE_A(tj + 1);

        const float2* cur = sh2[tj & 1];

        // ---- Phase B: two jj-half passes, pipes interleaved per item ----
        #pragma unroll 1
        for (int h = 0; h < 2; ++h) {
            ull ajP[HJ];                      // packed (re, im) j-side accum
            #pragma unroll
            for (int q = 0; q < HJ; ++q) ajP[q] = 0ull;

            #pragma unroll
            for (int jj = 0; jj < HJ; ++jj) {
                #pragma unroll
                for (int ii = 0; ii < T; ++ii) {
                    const float2 ra = cur[ii * T + h * HJ + jj];  // LDS.64
                    const float ph = k * ra.x;
                    float s, c, av;
                    if (ii < F_MUFU) {
                        // MUFU path
                        s = __sinf(ph);
                        c = __cosf(ph);
                        av = ra.y;
                    } else {
                        // FMA path: reduce to [-pi/2, pi/2] (single-word pi:
                        // err <= |n|*8.7e-8 ~ 7e-6 rad, under tolerance),
                        // packed Taylor; (-1)^n sign folded into amp (one
                        // scalar XOR on the ALU pipe)
                        const float q  = fmaf(ph, 0.31830988618379067f, 12582912.0f);
                        const float nf = q - 12582912.0f;
                        const float x  = fmaf(nf, -3.14159274101257f, ph);
                        const ull xs = pack2(x, x);
                        const ull xx = mul2(xs, xs);                  // (x2, x2)
                        ull p = fma2(xx, P5, P4);
                        p = fma2(xx, p, P3);
                        p = fma2(xx, p, P2);
                        p = fma2(xx, p, P1);
                        p = fma2(xx, p, P0);                          // (cos, sin/x)
                        float plo, phi;
                        unpack2(p, plo, phi);
                        c = plo;
                        s = x * phi;
                        const unsigned sgn = (__float_as_uint(q) & 1u) << 31;
                        av = __uint_as_float(__float_as_uint(ra.y) ^ sgn);
                    }
                    const ull cs = pack2(c, s);
                    const ull a2 = pack2(av, av);       // amp splat
                    aiP[ii] = fma2(cs, a2, aiP[ii]);
                    ajP[jj] = fma2(cs, a2, ajP[jj]);
                }
            }

            // flush this jj-half (diagonal tile skipped: its ajP is unused)
            if (tj != ti) {
                #pragma unroll
                for (int jj = 0; jj < HJ; ++jj) {
                    const int jglob = h * HJ + jj;
                    float re, im;
                    unpack2(ajP[jj], re, im);
                    float* p = out + ((size_t)(b * N_PTS) + tj * T + jglob) * (2 * N_WAVES)
                                   + 2 * tid;
                    red_add_v2(p, re, im);
                }
            }
        }

        __syncthreads();   // Phase B reads done before buffer is overwritten
    }

    // flush i-side partials once per block (validity already folded in)
    #pragma unroll
    for (int ii = 0; ii < T; ++ii) {
        float re, im;
        unpack2(aiP[ii], re, im);
        float* p = out + ((size_t)(b * N_PTS) + ti * T + ii) * (2 * N_WAVES)
                       + 2 * tid;
        red_add_v2(p, re, im);
    }
}

extern "C" void kernel_launch(void* const* d_in, const int* in_sizes, int n_in,
                              void* d_out, int out_size)
{
    const float* coords       = (const float*)d_in[0];
    const unsigned char* mask = (const unsigned char*)d_in[1];
    float* out                = (float*)d_out;

    const int BN = in_sizes[1];        // B * N
    const int B  = BN / N_PTS;

    // output is accumulated atomically -> must start from zero
    cudaMemsetAsync(d_out, 0, (size_t)out_size * sizeof(float), 0);

    dim3 grid(NSTRIPS, NT, B);
    spatial_embedding_sym_kernel<<<grid, 256>>>(coords, mask, out);
}

// round 16
// speedup vs baseline: 1.0732x; 1.0552x over previous
#include <cuda_runtime.h>
#include <math.h>

// Problem constants (fixed by setup_inputs: B=4, N=2048, D_MODEL=512)
#define N_PTS   2048
#define N_WAVES 256              // D_MODEL / 2
#define T       16               // tile rows
#define HJ      8                // jj-half width (j accums live per half)
#define NT      (N_PTS / T)      // 128 tiles
#define NSTRIPS 8                // offset-groups of 8 offsets each
#define F_MUFU  13               // ii < F_MUFU -> MUFU path, else FMA poly path

typedef unsigned long long ull;

__device__ __forceinline__ void red_add_v2(float* p, float x, float y) {
    asm volatile("red.global.add.v2.f32 [%0], {%1, %2};"
                 :: "l"(p), "f"(x), "f"(y) : "memory");
}
__device__ __forceinline__ ull pack2(float lo, float hi) {
    ull v; asm("mov.b64 %0, {%1, %2};" : "=l"(v) : "f"(lo), "f"(hi)); return v;
}
__device__ __forceinline__ void unpack2(ull v, float& lo, float& hi) {
    asm("mov.b64 {%0, %1}, %2;" : "=f"(lo), "=f"(hi) : "l"(v));
}
__device__ __forceinline__ ull fma2(ull a, ull b, ull c) {
    ull d; asm("fma.rn.f32x2 %0, %1, %2, %3;" : "=l"(d) : "l"(a), "l"(b), "l"(c));
    return d;
}
__device__ __forceinline__ ull mul2(ull a, ull b) {
    ull d; asm("mul.rn.f32x2 %0, %1, %2;" : "=l"(d) : "l"(a), "l"(b));
    return d;
}

// Balanced mapping: block (s, ti) handles tj = (ti + 8s + w) mod 128, w=0..7.
// Offsets d=1..63 cover each unordered tile pair exactly once; d=0 is the
// diagonal tile (i-side only); gap-64 pairs are an extra tile on blocks with
// ti<64 and (ti&7)==s. Every block runs 8 or 9 tiles -> uniform waves.
__global__ __launch_bounds__(256, 4) void spatial_embedding_sym_kernel(
    const float* __restrict__ coords,          // (B, N, 3)
    const unsigned char* __restrict__ mask,    // (B, N) bool, 1 = padded
    float* __restrict__ out)                   // (B, N, 512), pre-zeroed
{
    // Pair table: (r, amp) only. amp = 1/(4*pi*r)*vi*vj, zeroed at self-pairs.
    // j-side uses the SAME amp: wrong only on the diagonal tile, whose j-side
    // flush is skipped entirely, so the error is never observed.
    __shared__ float2 sh2[2][T * T];           // double-buffered (r, amp)
    __shared__ float sxi[T], syi[T], szi[T], svi[T];

    const int s   = blockIdx.x;                // offset group
    const int ti  = blockIdx.y;
    const int b   = blockIdx.z;
    const int tid = threadIdx.x;               // wave index m

    const int d0      = 8 * s;                 // first offset of this group
    const int nt_extra = ((ti < 64) && ((ti & 7) == s)) ? 1 : 0;
    const int ntiles  = 8 + nt_extra;

    const float* cb = coords + (size_t)b * N_PTS * 3;
    const unsigned char* mb = mask + (size_t)b * N_PTS;

    // k_m = 2*pi / lam_m, lam = geomspace(2, 100, 256) = 2 * 50^t
    //  => k = pi * 50^(-t), t = m/255. exp2f with two-word log2(50).
    const float tf = (float)tid * (1.0f / 255.0f);
    const float ex = fmaf(tf, -1.35934586e-8f, tf * -5.64385605f);
    const float k  = 3.14159265358979f * exp2f(ex);

    // packed Taylor coefficients: (cos_n, sin_n) for powers of x^2, |x|<=pi/2
    const ull P0 = pack2( 1.0f,            1.0f);
    const ull P1 = pack2(-0.5f,           -1.66666672e-1f);
    const ull P2 = pack2( 4.16666679e-2f,  8.33333358e-3f);
    const ull P3 = pack2(-1.38888893e-3f, -1.98412701e-4f);
    const ull P4 = pack2( 2.48015876e-5f,  2.75573192e-6f);
    const ull P5 = pack2(-2.75573192e-7f, -2.50521084e-8f);

    if (tid < T) {
        const int ig = ti * T + tid;
        sxi[tid] = cb[ig * 3 + 0];
        syi[tid] = cb[ig * 3 + 1];
        szi[tid] = cb[ig * 3 + 2];
        svi[tid] = (mb[ig] == 0) ? 1.0f : 0.0f;
    }

    // i-side packed (re, im) accumulators, persist across all tiles (32 regs)
    ull aiP[T];
    #pragma unroll
    for (int q = 0; q < T; ++q) aiP[q] = 0ull;

    const int pa_ii = tid >> 4;                // this thread's Phase-A pair
    const int pa_jj = tid & (T - 1);

    __syncthreads();                           // sxi/svi visible

    // ---- Phase A for tile t -> sh2[buf]; validities folded into amp ----
    #define PHASE_A(t, buf)                                                   \
    {                                                                         \
        const int jg = (t) * T + pa_jj;                                       \
        const float xj = cb[jg * 3 + 0];                                      \
        const float yj = cb[jg * 3 + 1];                                      \
        const float zj = cb[jg * 3 + 2];                                      \
        const float vj = (mb[jg] == 0) ? 1.0f : 0.0f;                         \
        const float dx = sxi[pa_ii] - xj;                                     \
        const float dy = syi[pa_ii] - yj;                                     \
        const float dz = szi[pa_ii] - zj;                                     \
        float sq = fmaf(dx, dx, fmaf(dy, dy, dz * dz));                       \
        const bool self = ((t) == ti) && (pa_ii == pa_jj);                    \
        if (self) sq = 1.0f;                       /* sq_safe */              \
        const float rs = rsqrtf(sq);                                          \
        const float r  = sq * rs;                                             \
        const float vv = self ? 0.0f : (svi[pa_ii] * vj);                     \
        const float amp = 0.07957747154594767f * rs * vv;                     \
        sh2[(buf)][tid] = make_float2(r, amp);                                \
    }

    // tj for tile index w: w<8 -> (ti + d0 + w) & 127; w==8 -> ti + 64
    #define TJ_OF(w) (((w) < 8) ? ((ti + d0 + (w)) & (NT - 1)) : ((ti + 64) & (NT - 1)))

    PHASE_A(TJ_OF(0), 0);                      // prologue
    __syncthreads();

    for (int w = 0; w < ntiles; ++w) {
        const int tj = TJ_OF(w);
        // pipeline: build next tile's table while sweeping current one
        if (w + 1 < ntiles) {
            const int tjn = TJ_OF(w + 1);
            PHASE_A(tjn, (w + 1) & 1);
        }

        const float2* cur = sh2[w & 1];

        // ---- Phase B: two jj-half passes, pipes interleaved per item ----
        #pragma unroll 1
        for (int h = 0; h < 2; ++h) {
            ull ajP[HJ];                      // packed (re, im) j-side accum
            #pragma unroll
            for (int q = 0; q < HJ; ++q) ajP[q] = 0ull;

            #pragma unroll
            for (int jj = 0; jj < HJ; ++jj) {
                #pragma unroll
                for (int ii = 0; ii < T; ++ii) {
                    const float2 ra = cur[ii * T + h * HJ + jj];  // LDS.64
                    const float ph = k * ra.x;
                    float s_, c_;
                    if (ii < F_MUFU) {
                        // MUFU path
                        s_ = __sinf(ph);
                        c_ = __cosf(ph);
                    } else {
                        // FMA path: reduce to [-pi/2, pi/2], packed Taylor,
                        // (-1)^n sign fixup on the ALU pipe
                        const float q  = fmaf(ph, 0.31830988618379067f, 12582912.0f);
                        const float nf = q - 12582912.0f;
                        float x = fmaf(nf, -3.14159274101257f, ph);   // -pi_hi
                        x = fmaf(nf, 8.742277657e-8f, x);             // -pi_lo
                        const ull xs = pack2(x, x);
                        const ull xx = mul2(xs, xs);                  // (x2, x2)
                        ull p = fma2(xx, P5, P4);
                        p = fma2(xx, p, P3);
                        p = fma2(xx, p, P2);
                        p = fma2(xx, p, P1);
                        p = fma2(xx, p, P0);                          // (cos, sin/x)
                        const ull sgn32 = (ull)((__float_as_uint(q) & 1u) << 31);
                        p ^= (sgn32 << 32) | sgn32;                   // *(-1)^n both
                        float plo, phi;
                        unpack2(p, plo, phi);
                        c_ = plo;
                        s_ = x * phi;
                    }
                    const ull cs = pack2(c_, s_);
                    const ull a2 = pack2(ra.y, ra.y);   // shared amp splat
                    aiP[ii] = fma2(cs, a2, aiP[ii]);
                    ajP[jj] = fma2(cs, a2, ajP[jj]);
                }
            }

            // flush this jj-half (diagonal tile skipped: its ajP is unused)
            if (tj != ti) {
                #pragma unroll
                for (int jj = 0; jj < HJ; ++jj) {
                    const int jglob = h * HJ + jj;
                    float re, im;
                    unpack2(ajP[jj], re, im);
                    float* p = out + ((size_t)(b * N_PTS) + tj * T + jglob) * (2 * N_WAVES)
                                   + 2 * tid;
                    red_add_v2(p, re, im);
                }
            }
        }

        __syncthreads();   // Phase B reads done before buffer is overwritten
    }

    // flush i-side partials once per block (validity already folded in)
    #pragma unroll
    for (int ii = 0; ii < T; ++ii) {
        float re, im;
        unpack2(aiP[ii], re, im);
        float* p = out + ((size_t)(b * N_PTS) + ti * T + ii) * (2 * N_WAVES)
                       + 2 * tid;
        red_add_v2(p, re, im);
    }
}

extern "C" void kernel_launch(void* const* d_in, const int* in_sizes, int n_in,
                              void* d_out, int out_size)
{
    const float* coords       = (const float*)d_in[0];
    const unsigned char* mask = (const unsigned char*)d_in[1];
    float* out                = (float*)d_out;

    const int BN = in_sizes[1];        // B * N
    const int B  = BN / N_PTS;

    // output is accumulated atomically -> must start from zero
    cudaMemsetAsync(d_out, 0, (size_t)out_size * sizeof(float), 0);

    dim3 grid(NSTRIPS, NT, B);
    spatial_embedding_sym_kernel<<<grid, 256>>>(coords, mask, out);
}